// round 13
// baseline (speedup 1.0000x reference)
#include <cuda_runtime.h>
#include <cstdint>
#include <cstddef>

// Problem constants
#define BATCH 2
#define SEQ   2048
#define DM    768
#define NH    12
#define DHD   64
#define ATT_SCALE 0.125f   // 1/sqrt(64)
#define KSPLIT 4
#define KEYS_PER_SPLIT (SEQ / KSPLIT)   // 512

// Scratch (allocation-free rule: __device__ globals)
__device__ float g_q[BATCH * SEQ * DM];
__device__ float g_k[BATCH * SEQ * DM];
__device__ float g_v[BATCH * SEQ * DM];
__device__ float g_attn[BATCH * SEQ * DM];
__device__ float g_rowl[BATCH * NH * SEQ];   // softmax row sums

// ---------------------------------------------------------------------------
// helpers
// ---------------------------------------------------------------------------
__device__ __forceinline__ uint32_t f2tf32(float f) {
    uint32_t u;
    asm("cvt.rna.tf32.f32 %0, %1;" : "=r"(u) : "f"(f));
    return u;
}

__device__ __forceinline__ void mma8(float* c, const uint32_t* a, const uint32_t* b) {
    asm volatile(
        "mma.sync.aligned.m16n8k8.row.col.f32.tf32.tf32.f32 "
        "{%0,%1,%2,%3},{%4,%5,%6,%7},{%8,%9},{%0,%1,%2,%3};"
        : "+f"(c[0]), "+f"(c[1]), "+f"(c[2]), "+f"(c[3])
        : "r"(a[0]), "r"(a[1]), "r"(a[2]), "r"(a[3]), "r"(b[0]), "r"(b[1]));
}

__device__ __forceinline__ uint32_t smem_u32(const void* p) {
    uint32_t a;
    asm("{ .reg .u64 t; cvta.to.shared.u64 t, %1; cvt.u32.u64 %0, t; }"
        : "=r"(a) : "l"(p));
    return a;
}

__device__ __forceinline__ void cp16(uint32_t dst, const void* src) {
    asm volatile("cp.async.cg.shared.global [%0], [%1], 16;" :: "r"(dst), "l"(src));
}
__device__ __forceinline__ void cp_commit() {
    asm volatile("cp.async.commit_group;");
}
template <int N>
__device__ __forceinline__ void cp_wait() {
    asm volatile("cp.async.wait_group %0;" :: "n"(N));
}

// ===========================================================================
// init: zero row sums and O accumulator
// ===========================================================================
__global__ void init_zero()
{
    int i = blockIdx.x * 256 + threadIdx.x;
    if (i < BATCH * NH * SEQ) g_rowl[i] = 0.f;
    if (i < BATCH * SEQ * DM) g_attn[i] = 0.f;
}

// ===========================================================================
// Projection core: 64x128 CTA tile, BK=32, 3-stage cp.async pipeline.
// (unchanged from R7 — proven)
// ===========================================================================
#define PJ_BK   32
#define PJ_ROWP 36
#define PJ_ASTG (64 * PJ_ROWP)
#define PJ_BSTG (128 * PJ_ROWP)
#define PJ_STGW (PJ_ASTG + PJ_BSTG)
#define PJ_NK   (DM / PJ_BK)
#define PJ_SMEM_BYTES (3 * PJ_STGW * 4)

__device__ __forceinline__ void proj_body(
    const float* __restrict__ X, const float* __restrict__ W,
    const float* __restrict__ bias, float* __restrict__ Y,
    int row0, int col0, float* sm)
{
    const int tid = threadIdx.x, lane = tid & 31, warp = tid >> 5;
    const int g = lane >> 2, lq = lane & 3;
    const int wm0 = (warp & 1) * 32, wn0 = (warp >> 1) * 32;
    const float* Ag = X + (size_t)row0 * DM;
    const float* Bg = W + (size_t)col0 * DM;

    auto issue = [&](int s) {
        float* Ast = sm + (s % 3) * PJ_STGW;
        float* Bst = Ast + PJ_ASTG;
        const int k0 = s * PJ_BK;
        #pragma unroll
        for (int t = 0; t < 2; t++) {
            int i = tid + t * 256;
            int r = i >> 3, cf = (i & 7) * 4;
            cp16(smem_u32(Ast + r * PJ_ROWP + cf), Ag + (size_t)r * DM + k0 + cf);
        }
        #pragma unroll
        for (int t = 0; t < 4; t++) {
            int i = tid + t * 256;
            int r = i >> 3, cf = (i & 7) * 4;
            cp16(smem_u32(Bst + r * PJ_ROWP + cf), Bg + (size_t)r * DM + k0 + cf);
        }
    };

    float acc[2][4][4] = {};

    auto compute = [&](int s) {
        const float* Ast = sm + (s % 3) * PJ_STGW;
        const float* Bst = Ast + PJ_ASTG;
        #pragma unroll
        for (int ksg = 0; ksg < PJ_BK / 8; ksg++) {
            const int kb = ksg * 8 + lq;
            uint32_t af[2][4], bf[4][2];
            #pragma unroll
            for (int mt = 0; mt < 2; mt++) {
                int m = wm0 + mt * 16 + g;
                af[mt][0] = f2tf32(Ast[m * PJ_ROWP + kb]);
                af[mt][1] = f2tf32(Ast[(m + 8) * PJ_ROWP + kb]);
                af[mt][2] = f2tf32(Ast[m * PJ_ROWP + kb + 4]);
                af[mt][3] = f2tf32(Ast[(m + 8) * PJ_ROWP + kb + 4]);
            }
            #pragma unroll
            for (int nt = 0; nt < 4; nt++) {
                int n = wn0 + nt * 8 + g;
                bf[nt][0] = f2tf32(Bst[n * PJ_ROWP + kb]);
                bf[nt][1] = f2tf32(Bst[n * PJ_ROWP + kb + 4]);
            }
            #pragma unroll
            for (int mt = 0; mt < 2; mt++)
                #pragma unroll
                for (int nt = 0; nt < 4; nt++)
                    mma8(acc[mt][nt], af[mt], bf[nt]);
        }
    };

    issue(0); cp_commit();
    issue(1); cp_commit();

    for (int s = 0; s < PJ_NK; s++) {
        cp_wait<1>();
        __syncthreads();
        if (s + 2 < PJ_NK) issue(s + 2);
        cp_commit();
        compute(s);
    }

    #pragma unroll
    for (int mt = 0; mt < 2; mt++) {
        int r = row0 + wm0 + mt * 16 + g;
        #pragma unroll
        for (int nt = 0; nt < 4; nt++) {
            int ccol = col0 + wn0 + nt * 8 + 2 * lq;
            float2 bv = *(const float2*)&bias[ccol];
            float2 o0 = { acc[mt][nt][0] + bv.x, acc[mt][nt][1] + bv.y };
            float2 o1 = { acc[mt][nt][2] + bv.x, acc[mt][nt][3] + bv.y };
            *(float2*)&Y[(size_t)r * DM + ccol]       = o0;
            *(float2*)&Y[(size_t)(r + 8) * DM + ccol] = o1;
        }
    }
}

__global__ __launch_bounds__(256, 2) void qkv_proj(
    const float* __restrict__ q,  const float* __restrict__ k,
    const float* __restrict__ v,
    const float* __restrict__ wq, const float* __restrict__ bq,
    const float* __restrict__ wk, const float* __restrict__ bk,
    const float* __restrict__ wv, const float* __restrict__ bv)
{
    extern __shared__ float psm[];
    const int z = blockIdx.z;
    const float* X = (z == 0) ? q  : (z == 1) ? k  : v;
    const float* W = (z == 0) ? wq : (z == 1) ? wk : wv;
    const float* B = (z == 0) ? bq : (z == 1) ? bk : bv;
    float*       Y = (z == 0) ? g_q : (z == 1) ? g_k : g_v;
    proj_body(X, W, B, Y, blockIdx.y * 64, blockIdx.x * 128, psm);
}

__global__ __launch_bounds__(256, 2) void o_proj(
    const float* __restrict__ W, const float* __restrict__ bias,
    float* __restrict__ Y)
{
    extern __shared__ float psm[];
    proj_body(g_attn, W, bias, Y, blockIdx.y * 64, blockIdx.x * 128, psm);
}

// ===========================================================================
// scores_exp v4: 128q x 64k CTA tile, 3 CTAs/SM.
// P = mask * exp((Q.K^T)*scale) (UNNORMALIZED), rowsums into g_rowl.
// cp.async tile loads, raw fp32 smem, cvt at fragment load.
// grid = (32 key-blocks, 16 q-blocks, 24) = 12288 CTAs, 256 thr, warps 2x4.
// Smem: Qst[128][68] + Kst[64][68] = 52224 B.
// ===========================================================================
#define SC_ROWP 68
#define SC_QTILE (128 * SC_ROWP)           // 8704 words
#define SC_KTILE (64 * SC_ROWP)            // 4352 words
#define SMS_BYTES ((SC_QTILE + SC_KTILE) * 4)   // 52224

__global__ __launch_bounds__(256, 3) void scores_exp(
    const int* __restrict__ mask, float* __restrict__ P)
{
    extern __shared__ float ssm[];
    float* Qst = ssm;
    float* Kst = ssm + SC_QTILE;
    __shared__ float srow[128];

    const int tid = threadIdx.x, lane = tid & 31, warp = tid >> 5;
    const int g = lane >> 2, lq = lane & 3;
    const int wm0 = (warp & 1) * 64, wn0 = (warp >> 1) * 16;
    const int z = blockIdx.z, b = z / NH, h = z % NH;
    const int q0 = blockIdx.y * 128, c0 = blockIdx.x * 64;

    const float* Qg = g_q + (size_t)b * SEQ * DM + h * DHD;
    const float* Kg = g_k + (size_t)b * SEQ * DM + h * DHD;

    if (tid < 128) srow[tid] = 0.f;

    // Q: 128 rows x 64 cols = 2048 float4 (8/thread); K: 64 rows = 1024 (4/thread)
    #pragma unroll
    for (int t = 0; t < 8; t++) {
        int i = tid + t * 256;
        int r = i >> 4, cf = (i & 15) * 4;
        cp16(smem_u32(Qst + r * SC_ROWP + cf), Qg + (size_t)(q0 + r) * DM + cf);
    }
    #pragma unroll
    for (int t = 0; t < 4; t++) {
        int i = tid + t * 256;
        int r = i >> 4, cf = (i & 15) * 4;
        cp16(smem_u32(Kst + r * SC_ROWP + cf), Kg + (size_t)(c0 + r) * DM + cf);
    }
    cp_commit();
    cp_wait<0>();
    __syncthreads();

    float acc[4][2][4] = {};
    #pragma unroll
    for (int ksg = 0; ksg < 8; ksg++) {
        const int kb = ksg * 8 + lq;
        uint32_t af[4][4], bf[2][2];
        #pragma unroll
        for (int mt = 0; mt < 4; mt++) {
            int m = wm0 + mt * 16 + g;
            af[mt][0] = f2tf32(Qst[m * SC_ROWP + kb]);
            af[mt][1] = f2tf32(Qst[(m + 8) * SC_ROWP + kb]);
            af[mt][2] = f2tf32(Qst[m * SC_ROWP + kb + 4]);
            af[mt][3] = f2tf32(Qst[(m + 8) * SC_ROWP + kb + 4]);
        }
        #pragma unroll
        for (int nt = 0; nt < 2; nt++) {
            int n = wn0 + nt * 8 + g;
            bf[nt][0] = f2tf32(Kst[n * SC_ROWP + kb]);
            bf[nt][1] = f2tf32(Kst[n * SC_ROWP + kb + 4]);
        }
        #pragma unroll
        for (int mt = 0; mt < 4; mt++)
            #pragma unroll
            for (int nt = 0; nt < 2; nt++)
                mma8(acc[mt][nt], af[mt], bf[nt]);
    }

    const int* mrow = mask + b * SEQ;
    float* C = P + (size_t)z * SEQ * SEQ;
    float rs[4][2] = {};
    #pragma unroll
    for (int nt = 0; nt < 2; nt++) {
        int ccol = c0 + wn0 + nt * 8 + 2 * lq;
        float m0 = (mrow[ccol] != 0) ? 1.f : 0.f;
        float m1 = (mrow[ccol + 1] != 0) ? 1.f : 0.f;
        #pragma unroll
        for (int mt = 0; mt < 4; mt++) {
            int r = q0 + wm0 + mt * 16 + g;
            float p0 = m0 * __expf(acc[mt][nt][0] * ATT_SCALE);
            float p1 = m1 * __expf(acc[mt][nt][1] * ATT_SCALE);
            float p2 = m0 * __expf(acc[mt][nt][2] * ATT_SCALE);
            float p3 = m1 * __expf(acc[mt][nt][3] * ATT_SCALE);
            float2 w0 = { p0, p1 }, w1 = { p2, p3 };
            *(float2*)&C[(size_t)r * SEQ + ccol]       = w0;
            *(float2*)&C[(size_t)(r + 8) * SEQ + ccol] = w1;
            rs[mt][0] += p0 + p1;
            rs[mt][1] += p2 + p3;
        }
    }

    #pragma unroll
    for (int mt = 0; mt < 4; mt++)
        #pragma unroll
        for (int hh = 0; hh < 2; hh++) {
            float v = rs[mt][hh];
            v += __shfl_xor_sync(0xffffffffu, v, 1);
            v += __shfl_xor_sync(0xffffffffu, v, 2);
            if (lq == 0)
                atomicAdd(&srow[wm0 + mt * 16 + hh * 8 + g], v);
        }
    __syncthreads();
    if (tid < 128)
        atomicAdd(&g_rowl[(size_t)z * SEQ + q0 + tid], srow[tid]);
}

// ===========================================================================
// pv_norm (exact R7 form — proven): cp.async 4-stage pipeline, 32-key
// chunks; reads raw P, writes normalized probs in place,
// O = (P V) * inv_l -> atomicAdd into g_attn.  grid (16, 4, 24).
// ===========================================================================
#define PV_CH      32
#define PV_NCHUNK  (KEYS_PER_SPLIT / PV_CH)   // 16
#define PV_PROW    36
#define PV_VROW    72
#define PV_PSTG    (128 * PV_PROW)            // 4608 words
#define PV_VSTG    (PV_CH * PV_VROW)          // 2304 words
#define PV_STGW    (PV_PSTG + PV_VSTG)        // 6912 words
#define PV_SMEM_BYTES (4 * PV_STGW * 4 + 512) // 111104

__global__ __launch_bounds__(256, 2) void pv_norm(float* __restrict__ probs)
{
    extern __shared__ float sm[];
    float* inv_l = sm + 4 * PV_STGW;

    const int tid = threadIdx.x, lane = tid & 31, warp = tid >> 5;
    const int g = lane >> 2, lq = lane & 3;
    const int wm0 = (warp & 3) * 32, wn0 = (warp >> 2) * 32;
    const int z = blockIdx.z, b = z / NH, h = z % NH;
    const int q0 = blockIdx.x * 128;
    const int k_base = blockIdx.y * KEYS_PER_SPLIT;

    float* Pg = probs + (size_t)z * SEQ * SEQ + (size_t)q0 * SEQ;
    const float* Vg = g_v + (size_t)b * SEQ * DM + h * DHD;

    if (tid < 128)
        inv_l[tid] = 1.f / g_rowl[(size_t)z * SEQ + q0 + tid];

    auto issue = [&](int ch) {
        float* Pst = sm + (ch & 3) * PV_STGW;
        float* Vst = Pst + PV_PSTG;
        const int kb0 = k_base + ch * PV_CH;
        #pragma unroll
        for (int t = 0; t < 4; t++) {
            int i = tid + t * 256;
            int r = i >> 3, cf = (i & 7) * 4;
            cp16(smem_u32(Pst + r * PV_PROW + cf),
                 Pg + (size_t)r * SEQ + kb0 + cf);
        }
        #pragma unroll
        for (int t = 0; t < 2; t++) {
            int i = tid + t * 256;
            int k = i >> 4, cf = (i & 15) * 4;
            cp16(smem_u32(Vst + k * PV_VROW + cf),
                 Vg + (size_t)(kb0 + k) * DM + cf);
        }
    };

    issue(0); cp_commit();
    issue(1); cp_commit();
    issue(2); cp_commit();

    float oacc[2][4][4] = {};

    for (int c = 0; c < PV_NCHUNK; c++) {
        cp_wait<2>();
        __syncthreads();
        if (c + 3 < PV_NCHUNK) issue(c + 3);
        cp_commit();

        float* Pst = sm + (c & 3) * PV_STGW;
        float* Vst = Pst + PV_PSTG;

        #pragma unroll
        for (int ksg = 0; ksg < 4; ksg++) {
            const int kb = ksg * 8 + lq;
            uint32_t af[2][4], bf[4][2];
            #pragma unroll
            for (int mt = 0; mt < 2; mt++) {
                int m = wm0 + mt * 16 + g;
                af[mt][0] = f2tf32(Pst[m * PV_PROW + kb]);
                af[mt][1] = f2tf32(Pst[(m + 8) * PV_PROW + kb]);
                af[mt][2] = f2tf32(Pst[m * PV_PROW + kb + 4]);
                af[mt][3] = f2tf32(Pst[(m + 8) * PV_PROW + kb + 4]);
            }
            #pragma unroll
            for (int nt = 0; nt < 4; nt++) {
                int n = wn0 + nt * 8 + g;
                bf[nt][0] = f2tf32(Vst[kb * PV_VROW + n]);
                bf[nt][1] = f2tf32(Vst[(kb + 4) * PV_VROW + n]);
            }
            #pragma unroll
            for (int mt = 0; mt < 2; mt++)
                #pragma unroll
                for (int nt = 0; nt < 4; nt++)
                    mma8(oacc[mt][nt], af[mt], bf[nt]);
        }

        const int kb0 = k_base + c * PV_CH;
        #pragma unroll
        for (int t = 0; t < 4; t++) {
            int i = tid + t * 256;
            int r = i >> 3, cf = (i & 7) * 4;
            float4 v = *(const float4*)(Pst + r * PV_PROW + cf);
            float iv = inv_l[r];
            float4 w = { v.x * iv, v.y * iv, v.z * iv, v.w * iv };
            *(float4*)(Pg + (size_t)r * SEQ + kb0 + cf) = w;
        }
    }

    float* Og = g_attn + (size_t)b * SEQ * DM + h * DHD + (size_t)q0 * DM;
    #pragma unroll
    for (int mt = 0; mt < 2; mt++) {
        int r = wm0 + mt * 16 + g;
        float i0 = inv_l[r], i1 = inv_l[r + 8];
        #pragma unroll
        for (int nt = 0; nt < 4; nt++) {
            int c = wn0 + nt * 8 + 2 * lq;
            atomicAdd(&Og[(size_t)r * DM + c],           oacc[mt][nt][0] * i0);
            atomicAdd(&Og[(size_t)r * DM + c + 1],       oacc[mt][nt][1] * i0);
            atomicAdd(&Og[(size_t)(r + 8) * DM + c],     oacc[mt][nt][2] * i1);
            atomicAdd(&Og[(size_t)(r + 8) * DM + c + 1], oacc[mt][nt][3] * i1);
        }
    }
}

// ---------------------------------------------------------------------------
extern "C" void kernel_launch(void* const* d_in, const int* in_sizes, int n_in,
                              void* d_out, int out_size)
{
    const float* query = (const float*)d_in[0];
    const float* key   = (const float*)d_in[1];
    const float* value = (const float*)d_in[2];
    const int*   mask  = (const int*)d_in[3];
    const float* wq = (const float*)d_in[4];
    const float* bq = (const float*)d_in[5];
    const float* wk = (const float*)d_in[6];
    const float* bk = (const float*)d_in[7];
    const float* wv = (const float*)d_in[8];
    const float* bv = (const float*)d_in[9];
    const float* wo = (const float*)d_in[10];
    const float* bo = (const float*)d_in[11];

    float* out   = (float*)d_out;                       // [B, S, D]
    float* probs = out + (size_t)BATCH * SEQ * DM;      // [B, H, S, S]

    cudaFuncSetAttribute(qkv_proj,
                         cudaFuncAttributeMaxDynamicSharedMemorySize, PJ_SMEM_BYTES);
    cudaFuncSetAttribute(o_proj,
                         cudaFuncAttributeMaxDynamicSharedMemorySize, PJ_SMEM_BYTES);
    cudaFuncSetAttribute(scores_exp,
                         cudaFuncAttributeMaxDynamicSharedMemorySize, SMS_BYTES);
    cudaFuncSetAttribute(pv_norm,
                         cudaFuncAttributeMaxDynamicSharedMemorySize, PV_SMEM_BYTES);

    init_zero<<<(BATCH * SEQ * DM + 255) / 256, 256>>>();

    dim3 qkv_grid(DM / 128, (BATCH * SEQ) / 64, 3);     // (6, 64, 3)
    qkv_proj<<<qkv_grid, 256, PJ_SMEM_BYTES>>>(query, key, value,
                                               wq, bq, wk, bk, wv, bv);

    dim3 sc_grid(SEQ / 64, SEQ / 128, BATCH * NH);      // (32, 16, 24)
    scores_exp<<<sc_grid, 256, SMS_BYTES>>>(mask, probs);

    dim3 pv_grid(SEQ / 128, KSPLIT, BATCH * NH);        // (16, 4, 24)
    pv_norm<<<pv_grid, 256, PV_SMEM_BYTES>>>(probs);

    dim3 o_grid(DM / 128, (BATCH * SEQ) / 64);          // (6, 64)
    o_proj<<<o_grid, 256, PJ_SMEM_BYTES>>>(wo, bo, out);
}

// round 17
// speedup vs baseline: 1.0624x; 1.0624x over previous
#include <cuda_runtime.h>
#include <cstdint>
#include <cstddef>

// Problem constants
#define BATCH 2
#define SEQ   2048
#define DM    768
#define NH    12
#define DHD   64
#define ATT_SCALE 0.125f   // 1/sqrt(64)
#define KSPLIT 4
#define KEYS_PER_SPLIT (SEQ / KSPLIT)   // 512

// Scratch (allocation-free rule: __device__ globals)
__device__ float g_q[BATCH * SEQ * DM];
__device__ float g_k[BATCH * SEQ * DM];
__device__ float g_v[BATCH * SEQ * DM];
__device__ float g_attn[BATCH * SEQ * DM];
__device__ float g_rowl[BATCH * NH * SEQ];   // softmax row sums

// ---------------------------------------------------------------------------
// helpers
// ---------------------------------------------------------------------------
__device__ __forceinline__ uint32_t f2tf32(float f) {
    uint32_t u;
    asm("cvt.rna.tf32.f32 %0, %1;" : "=r"(u) : "f"(f));
    return u;
}

__device__ __forceinline__ void mma8(float* c, const uint32_t* a, const uint32_t* b) {
    asm volatile(
        "mma.sync.aligned.m16n8k8.row.col.f32.tf32.tf32.f32 "
        "{%0,%1,%2,%3},{%4,%5,%6,%7},{%8,%9},{%0,%1,%2,%3};"
        : "+f"(c[0]), "+f"(c[1]), "+f"(c[2]), "+f"(c[3])
        : "r"(a[0]), "r"(a[1]), "r"(a[2]), "r"(a[3]), "r"(b[0]), "r"(b[1]));
}

__device__ __forceinline__ uint32_t smem_u32(const void* p) {
    uint32_t a;
    asm("{ .reg .u64 t; cvta.to.shared.u64 t, %1; cvt.u32.u64 %0, t; }"
        : "=r"(a) : "l"(p));
    return a;
}

__device__ __forceinline__ void cp16(uint32_t dst, const void* src) {
    asm volatile("cp.async.cg.shared.global [%0], [%1], 16;" :: "r"(dst), "l"(src));
}
__device__ __forceinline__ void cp_commit() {
    asm volatile("cp.async.commit_group;");
}
template <int N>
__device__ __forceinline__ void cp_wait() {
    asm volatile("cp.async.wait_group %0;" :: "n"(N));
}

// ===========================================================================
// Projection core: 64x128 CTA tile, BK=32, 3-stage cp.async pipeline.
// (unchanged from R7 — proven)
// ===========================================================================
#define PJ_BK   32
#define PJ_ROWP 36
#define PJ_ASTG (64 * PJ_ROWP)
#define PJ_BSTG (128 * PJ_ROWP)
#define PJ_STGW (PJ_ASTG + PJ_BSTG)
#define PJ_NK   (DM / PJ_BK)
#define PJ_SMEM_BYTES (3 * PJ_STGW * 4)

__device__ __forceinline__ void proj_body(
    const float* __restrict__ X, const float* __restrict__ W,
    const float* __restrict__ bias, float* __restrict__ Y,
    int row0, int col0, float* sm)
{
    const int tid = threadIdx.x, lane = tid & 31, warp = tid >> 5;
    const int g = lane >> 2, lq = lane & 3;
    const int wm0 = (warp & 1) * 32, wn0 = (warp >> 1) * 32;
    const float* Ag = X + (size_t)row0 * DM;
    const float* Bg = W + (size_t)col0 * DM;

    auto issue = [&](int s) {
        float* Ast = sm + (s % 3) * PJ_STGW;
        float* Bst = Ast + PJ_ASTG;
        const int k0 = s * PJ_BK;
        #pragma unroll
        for (int t = 0; t < 2; t++) {
            int i = tid + t * 256;
            int r = i >> 3, cf = (i & 7) * 4;
            cp16(smem_u32(Ast + r * PJ_ROWP + cf), Ag + (size_t)r * DM + k0 + cf);
        }
        #pragma unroll
        for (int t = 0; t < 4; t++) {
            int i = tid + t * 256;
            int r = i >> 3, cf = (i & 7) * 4;
            cp16(smem_u32(Bst + r * PJ_ROWP + cf), Bg + (size_t)r * DM + k0 + cf);
        }
    };

    float acc[2][4][4] = {};

    auto compute = [&](int s) {
        const float* Ast = sm + (s % 3) * PJ_STGW;
        const float* Bst = Ast + PJ_ASTG;
        #pragma unroll
        for (int ksg = 0; ksg < PJ_BK / 8; ksg++) {
            const int kb = ksg * 8 + lq;
            uint32_t af[2][4], bf[4][2];
            #pragma unroll
            for (int mt = 0; mt < 2; mt++) {
                int m = wm0 + mt * 16 + g;
                af[mt][0] = f2tf32(Ast[m * PJ_ROWP + kb]);
                af[mt][1] = f2tf32(Ast[(m + 8) * PJ_ROWP + kb]);
                af[mt][2] = f2tf32(Ast[m * PJ_ROWP + kb + 4]);
                af[mt][3] = f2tf32(Ast[(m + 8) * PJ_ROWP + kb + 4]);
            }
            #pragma unroll
            for (int nt = 0; nt < 4; nt++) {
                int n = wn0 + nt * 8 + g;
                bf[nt][0] = f2tf32(Bst[n * PJ_ROWP + kb]);
                bf[nt][1] = f2tf32(Bst[n * PJ_ROWP + kb + 4]);
            }
            #pragma unroll
            for (int mt = 0; mt < 2; mt++)
                #pragma unroll
                for (int nt = 0; nt < 4; nt++)
                    mma8(acc[mt][nt], af[mt], bf[nt]);
        }
    };

    issue(0); cp_commit();
    issue(1); cp_commit();

    for (int s = 0; s < PJ_NK; s++) {
        cp_wait<1>();
        __syncthreads();
        if (s + 2 < PJ_NK) issue(s + 2);
        cp_commit();
        compute(s);
    }

    #pragma unroll
    for (int mt = 0; mt < 2; mt++) {
        int r = row0 + wm0 + mt * 16 + g;
        #pragma unroll
        for (int nt = 0; nt < 4; nt++) {
            int ccol = col0 + wn0 + nt * 8 + 2 * lq;
            float2 bv = *(const float2*)&bias[ccol];
            float2 o0 = { acc[mt][nt][0] + bv.x, acc[mt][nt][1] + bv.y };
            float2 o1 = { acc[mt][nt][2] + bv.x, acc[mt][nt][3] + bv.y };
            *(float2*)&Y[(size_t)r * DM + ccol]       = o0;
            *(float2*)&Y[(size_t)(r + 8) * DM + ccol] = o1;
        }
    }
}

__global__ __launch_bounds__(256, 2) void qkv_proj(
    const float* __restrict__ q,  const float* __restrict__ k,
    const float* __restrict__ v,
    const float* __restrict__ wq, const float* __restrict__ bq,
    const float* __restrict__ wk, const float* __restrict__ bk,
    const float* __restrict__ wv, const float* __restrict__ bv)
{
    extern __shared__ float psm[];
    const int z = blockIdx.z;
    const float* X = (z == 0) ? q  : (z == 1) ? k  : v;
    const float* W = (z == 0) ? wq : (z == 1) ? wk : wv;
    const float* B = (z == 0) ? bq : (z == 1) ? bk : bv;
    float*       Y = (z == 0) ? g_q : (z == 1) ? g_k : g_v;
    proj_body(X, W, B, Y, blockIdx.y * 64, blockIdx.x * 128, psm);
}

__global__ __launch_bounds__(256, 2) void o_proj(
    const float* __restrict__ W, const float* __restrict__ bias,
    float* __restrict__ Y)
{
    extern __shared__ float psm[];
    proj_body(g_attn, W, bias, Y, blockIdx.y * 64, blockIdx.x * 128, psm);
}

// ===========================================================================
// scores_exp (exact R7 form — proven): P = mask * exp((Q.K^T)*scale)
// (UNNORMALIZED), rowsums into g_rowl. cp.async tile loads, raw fp32 smem,
// cvt at fragment load. grid = (16, 16, 24), 256 threads, warps 2x4.
// ===========================================================================
#define SC_ROWP 68
#define SC_TILE (128 * SC_ROWP)
#define SMS_BYTES (2 * SC_TILE * 4)

__global__ __launch_bounds__(256, 2) void scores_exp(
    const int* __restrict__ mask, float* __restrict__ P)
{
    extern __shared__ float ssm[];
    float* Qst = ssm;
    float* Kst = ssm + SC_TILE;
    __shared__ float srow[128];

    const int tid = threadIdx.x, lane = tid & 31, warp = tid >> 5;
    const int g = lane >> 2, lq = lane & 3;
    const int wm0 = (warp & 1) * 64, wn0 = (warp >> 1) * 32;
    const int z = blockIdx.z, b = z / NH, h = z % NH;
    const int q0 = blockIdx.y * 128, c0 = blockIdx.x * 128;

    const float* Qg = g_q + (size_t)b * SEQ * DM + h * DHD;
    const float* Kg = g_k + (size_t)b * SEQ * DM + h * DHD;

    if (tid < 128) srow[tid] = 0.f;

    #pragma unroll
    for (int t = 0; t < 8; t++) {
        int i = tid + t * 256;
        int r = i >> 4, cf = (i & 15) * 4;
        cp16(smem_u32(Qst + r * SC_ROWP + cf), Qg + (size_t)(q0 + r) * DM + cf);
        cp16(smem_u32(Kst + r * SC_ROWP + cf), Kg + (size_t)(c0 + r) * DM + cf);
    }
    cp_commit();
    cp_wait<0>();
    __syncthreads();

    float acc[4][4][4] = {};
    #pragma unroll
    for (int ksg = 0; ksg < 8; ksg++) {
        const int kb = ksg * 8 + lq;
        uint32_t af[4][4], bf[4][2];
        #pragma unroll
        for (int mt = 0; mt < 4; mt++) {
            int m = wm0 + mt * 16 + g;
            af[mt][0] = f2tf32(Qst[m * SC_ROWP + kb]);
            af[mt][1] = f2tf32(Qst[(m + 8) * SC_ROWP + kb]);
            af[mt][2] = f2tf32(Qst[m * SC_ROWP + kb + 4]);
            af[mt][3] = f2tf32(Qst[(m + 8) * SC_ROWP + kb + 4]);
        }
        #pragma unroll
        for (int nt = 0; nt < 4; nt++) {
            int n = wn0 + nt * 8 + g;
            bf[nt][0] = f2tf32(Kst[n * SC_ROWP + kb]);
            bf[nt][1] = f2tf32(Kst[n * SC_ROWP + kb + 4]);
        }
        #pragma unroll
        for (int mt = 0; mt < 4; mt++)
            #pragma unroll
            for (int nt = 0; nt < 4; nt++)
                mma8(acc[mt][nt], af[mt], bf[nt]);
    }

    const int* mrow = mask + b * SEQ;
    float* C = P + (size_t)z * SEQ * SEQ;
    float rs[4][2] = {};
    #pragma unroll
    for (int nt = 0; nt < 4; nt++) {
        int ccol = c0 + wn0 + nt * 8 + 2 * lq;
        float m0 = (mrow[ccol] != 0) ? 1.f : 0.f;
        float m1 = (mrow[ccol + 1] != 0) ? 1.f : 0.f;
        #pragma unroll
        for (int mt = 0; mt < 4; mt++) {
            int r = q0 + wm0 + mt * 16 + g;
            float p0 = m0 * __expf(acc[mt][nt][0] * ATT_SCALE);
            float p1 = m1 * __expf(acc[mt][nt][1] * ATT_SCALE);
            float p2 = m0 * __expf(acc[mt][nt][2] * ATT_SCALE);
            float p3 = m1 * __expf(acc[mt][nt][3] * ATT_SCALE);
            float2 w0 = { p0, p1 }, w1 = { p2, p3 };
            *(float2*)&C[(size_t)r * SEQ + ccol]       = w0;
            *(float2*)&C[(size_t)(r + 8) * SEQ + ccol] = w1;
            rs[mt][0] += p0 + p1;
            rs[mt][1] += p2 + p3;
        }
    }

    #pragma unroll
    for (int mt = 0; mt < 4; mt++)
        #pragma unroll
        for (int hh = 0; hh < 2; hh++) {
            float v = rs[mt][hh];
            v += __shfl_xor_sync(0xffffffffu, v, 1);
            v += __shfl_xor_sync(0xffffffffu, v, 2);
            if (lq == 0)
                atomicAdd(&srow[wm0 + mt * 16 + hh * 8 + g], v);
        }
    __syncthreads();
    if (tid < 128)
        atomicAdd(&g_rowl[(size_t)z * SEQ + q0 + tid], srow[tid]);
}

// ===========================================================================
// pv_norm (exact R7 form — proven): cp.async 4-stage pipeline, 32-key
// chunks; reads raw P, writes normalized probs in place,
// O = (P V) * inv_l -> atomicAdd into g_attn.  grid (16, 4, 24).
// ===========================================================================
#define PV_CH      32
#define PV_NCHUNK  (KEYS_PER_SPLIT / PV_CH)   // 16
#define PV_PROW    36
#define PV_VROW    72
#define PV_PSTG    (128 * PV_PROW)            // 4608 words
#define PV_VSTG    (PV_CH * PV_VROW)          // 2304 words
#define PV_STGW    (PV_PSTG + PV_VSTG)        // 6912 words
#define PV_SMEM_BYTES (4 * PV_STGW * 4 + 512) // 111104

__global__ __launch_bounds__(256, 2) void pv_norm(float* __restrict__ probs)
{
    extern __shared__ float sm[];
    float* inv_l = sm + 4 * PV_STGW;

    const int tid = threadIdx.x, lane = tid & 31, warp = tid >> 5;
    const int g = lane >> 2, lq = lane & 3;
    const int wm0 = (warp & 3) * 32, wn0 = (warp >> 2) * 32;
    const int z = blockIdx.z, b = z / NH, h = z % NH;
    const int q0 = blockIdx.x * 128;
    const int k_base = blockIdx.y * KEYS_PER_SPLIT;

    float* Pg = probs + (size_t)z * SEQ * SEQ + (size_t)q0 * SEQ;
    const float* Vg = g_v + (size_t)b * SEQ * DM + h * DHD;

    if (tid < 128)
        inv_l[tid] = 1.f / g_rowl[(size_t)z * SEQ + q0 + tid];

    auto issue = [&](int ch) {
        float* Pst = sm + (ch & 3) * PV_STGW;
        float* Vst = Pst + PV_PSTG;
        const int kb0 = k_base + ch * PV_CH;
        #pragma unroll
        for (int t = 0; t < 4; t++) {
            int i = tid + t * 256;
            int r = i >> 3, cf = (i & 7) * 4;
            cp16(smem_u32(Pst + r * PV_PROW + cf),
                 Pg + (size_t)r * SEQ + kb0 + cf);
        }
        #pragma unroll
        for (int t = 0; t < 2; t++) {
            int i = tid + t * 256;
            int k = i >> 4, cf = (i & 15) * 4;
            cp16(smem_u32(Vst + k * PV_VROW + cf),
                 Vg + (size_t)(kb0 + k) * DM + cf);
        }
    };

    issue(0); cp_commit();
    issue(1); cp_commit();
    issue(2); cp_commit();

    float oacc[2][4][4] = {};

    for (int c = 0; c < PV_NCHUNK; c++) {
        cp_wait<2>();
        __syncthreads();
        if (c + 3 < PV_NCHUNK) issue(c + 3);
        cp_commit();

        float* Pst = sm + (c & 3) * PV_STGW;
        float* Vst = Pst + PV_PSTG;

        #pragma unroll
        for (int ksg = 0; ksg < 4; ksg++) {
            const int kb = ksg * 8 + lq;
            uint32_t af[2][4], bf[4][2];
            #pragma unroll
            for (int mt = 0; mt < 2; mt++) {
                int m = wm0 + mt * 16 + g;
                af[mt][0] = f2tf32(Pst[m * PV_PROW + kb]);
                af[mt][1] = f2tf32(Pst[(m + 8) * PV_PROW + kb]);
                af[mt][2] = f2tf32(Pst[m * PV_PROW + kb + 4]);
                af[mt][3] = f2tf32(Pst[(m + 8) * PV_PROW + kb + 4]);
            }
            #pragma unroll
            for (int nt = 0; nt < 4; nt++) {
                int n = wn0 + nt * 8 + g;
                bf[nt][0] = f2tf32(Vst[kb * PV_VROW + n]);
                bf[nt][1] = f2tf32(Vst[(kb + 4) * PV_VROW + n]);
            }
            #pragma unroll
            for (int mt = 0; mt < 2; mt++)
                #pragma unroll
                for (int nt = 0; nt < 4; nt++)
                    mma8(oacc[mt][nt], af[mt], bf[nt]);
        }

        const int kb0 = k_base + c * PV_CH;
        #pragma unroll
        for (int t = 0; t < 4; t++) {
            int i = tid + t * 256;
            int r = i >> 3, cf = (i & 7) * 4;
            float4 v = *(const float4*)(Pst + r * PV_PROW + cf);
            float iv = inv_l[r];
            float4 w = { v.x * iv, v.y * iv, v.z * iv, v.w * iv };
            *(float4*)(Pg + (size_t)r * SEQ + kb0 + cf) = w;
        }
    }

    float* Og = g_attn + (size_t)b * SEQ * DM + h * DHD + (size_t)q0 * DM;
    #pragma unroll
    for (int mt = 0; mt < 2; mt++) {
        int r = wm0 + mt * 16 + g;
        float i0 = inv_l[r], i1 = inv_l[r + 8];
        #pragma unroll
        for (int nt = 0; nt < 4; nt++) {
            int c = wn0 + nt * 8 + 2 * lq;
            atomicAdd(&Og[(size_t)r * DM + c],           oacc[mt][nt][0] * i0);
            atomicAdd(&Og[(size_t)r * DM + c + 1],       oacc[mt][nt][1] * i0);
            atomicAdd(&Og[(size_t)(r + 8) * DM + c],     oacc[mt][nt][2] * i1);
            atomicAdd(&Og[(size_t)(r + 8) * DM + c + 1], oacc[mt][nt][3] * i1);
        }
    }
}

// ---------------------------------------------------------------------------
extern "C" void kernel_launch(void* const* d_in, const int* in_sizes, int n_in,
                              void* d_out, int out_size)
{
    const float* query = (const float*)d_in[0];
    const float* key   = (const float*)d_in[1];
    const float* value = (const float*)d_in[2];
    const int*   mask  = (const int*)d_in[3];
    const float* wq = (const float*)d_in[4];
    const float* bq = (const float*)d_in[5];
    const float* wk = (const float*)d_in[6];
    const float* bk = (const float*)d_in[7];
    const float* wv = (const float*)d_in[8];
    const float* bv = (const float*)d_in[9];
    const float* wo = (const float*)d_in[10];
    const float* bo = (const float*)d_in[11];

    float* out   = (float*)d_out;                       // [B, S, D]
    float* probs = out + (size_t)BATCH * SEQ * DM;      // [B, H, S, S]

    cudaFuncSetAttribute(qkv_proj,
                         cudaFuncAttributeMaxDynamicSharedMemorySize, PJ_SMEM_BYTES);
    cudaFuncSetAttribute(o_proj,
                         cudaFuncAttributeMaxDynamicSharedMemorySize, PJ_SMEM_BYTES);
    cudaFuncSetAttribute(scores_exp,
                         cudaFuncAttributeMaxDynamicSharedMemorySize, SMS_BYTES);
    cudaFuncSetAttribute(pv_norm,
                         cudaFuncAttributeMaxDynamicSharedMemorySize, PV_SMEM_BYTES);

    // init via async memsets (graph memset nodes; no alloc, no extra kernel)
    float *attn_p, *rowl_p;
    cudaGetSymbolAddress((void**)&attn_p, g_attn);
    cudaGetSymbolAddress((void**)&rowl_p, g_rowl);
    cudaMemsetAsync(attn_p, 0, (size_t)BATCH * SEQ * DM * sizeof(float));
    cudaMemsetAsync(rowl_p, 0, (size_t)BATCH * NH * SEQ * sizeof(float));

    dim3 qkv_grid(DM / 128, (BATCH * SEQ) / 64, 3);     // (6, 64, 3)
    qkv_proj<<<qkv_grid, 256, PJ_SMEM_BYTES>>>(query, key, value,
                                               wq, bq, wk, bk, wv, bv);

    dim3 sc_grid(SEQ / 128, SEQ / 128, BATCH * NH);     // (16, 16, 24)
    scores_exp<<<sc_grid, 256, SMS_BYTES>>>(mask, probs);

    dim3 pv_grid(SEQ / 128, KSPLIT, BATCH * NH);        // (16, 4, 24)
    pv_norm<<<pv_grid, 256, PV_SMEM_BYTES>>>(probs);

    dim3 o_grid(DM / 128, (BATCH * SEQ) / 64);          // (6, 64)
    o_proj<<<o_grid, 256, PJ_SMEM_BYTES>>>(wo, bo, out);
}